// round 8
// baseline (speedup 1.0000x reference)
#include <cuda_runtime.h>
#include <cstdint>

#define BATCH 384
#define FEAT  256
#define GROUP 8
#define RPB   3                  // pred rows per block
#define NBLK  (BATCH / RPB)      // 128 independent blocks (no grid barrier!)
#define NT    768                // 24 warps; each warp owns 16 gallery rows

__device__ float g_partial[NBLK];
__device__ unsigned g_done = 0;

__device__ __forceinline__ uint64_t pack2(float lo, float hi) {
    uint64_t r; asm("mov.b64 %0, {%1, %2};" : "=l"(r) : "f"(lo), "f"(hi)); return r;
}
__device__ __forceinline__ void unpack2(uint64_t v, float& lo, float& hi) {
    asm("mov.b64 {%0, %1}, %2;" : "=f"(lo), "=f"(hi) : "l"(v));
}
__device__ __forceinline__ void fma2(uint64_t& acc, uint64_t a, uint64_t b) {
    asm("fma.rn.f32x2 %0, %1, %2, %0;" : "+l"(acc) : "l"(a), "l"(b));
}
__device__ __forceinline__ float sigm(float d) {   // 1/(1+exp(clip(d*100)))
    float e = fminf(fmaxf(d * 100.0f, -50.0f), 50.0f);
    return __fdividef(1.0f, 1.0f + __expf(e));
}

__global__ __launch_bounds__(NT, 1) void smoothap_kernel(
        const float* __restrict__ preds,
        const float* __restrict__ gallery,
        float* __restrict__ out) {
    __shared__ __align__(16) uint64_t spp[RPB][FEAT / 2];  // raw pred k-pairs (3 KB)
    __shared__ float S[RPB][BATCH];          // final sims (4.5 KB); head doubles as staging
    __shared__ float wnorm[24];
    __shared__ float inv3[RPB];              // pred inverse norms
    __shared__ float wp[24][2][8];           // per-warp rank partials
    __shared__ float wfin[4];
    __shared__ unsigned islast;

    int tid  = threadIdx.x;
    int warp = tid >> 5, lane = tid & 31;
    int base = blockIdx.x * RPB;

    // ---------------- Phase 0: pred rows -> raw packed smem + inverse norms --
    float* praw = &S[0][0];                  // staging: 768 floats (fits 3x384)
    {
        float v = preds[base * FEAT + tid];  // tid covers 3 rows x 256
        praw[tid] = v;
        float ss = v * v;
        #pragma unroll
        for (int off = 16; off > 0; off >>= 1)
            ss += __shfl_down_sync(0xffffffffu, ss, off);
        if (lane == 0) wnorm[warp] = ss;     // warps r*8..r*8+7 belong to row r
    }
    __syncthreads();
    if (tid < RPB) {
        float ss = 0.f;
        #pragma unroll
        for (int w = 0; w < 8; w++) ss += wnorm[tid * 8 + w];
        inv3[tid] = 1.0f / fmaxf(sqrtf(ss), 1e-12f);
    }
    __syncthreads();
    if (tid < RPB * FEAT / 2) {              // pack raw pred k-pairs
        int r = tid / (FEAT / 2), i = tid % (FEAT / 2);
        uint64_t pp = pack2(praw[r * FEAT + 2 * i], praw[r * FEAT + 2 * i + 1]);
        __syncwarp();                        // praw read-before-overwrite (S alias safe: spp separate)
        spp[r][i] = pp;
    }
    __syncthreads();

    // ---- Phase A: each warp computes S[0..2][j] for its 16 gallery rows ----
    // 8-lane group per row j; lanes read gallery[j] row-wise coalesced.
    // Dot products AND g.g accumulated in one pass -> normalization applied at
    // the end (no transposed gallery, no grid barrier needed).
    int kl = (lane & 7) * 4;                 // this lane's k offset within 32-chunk
    #pragma unroll
    for (int b = 0; b < 4; b++) {
        int j = warp * 16 + b * 4 + (lane >> 3);
        const float4* gptr = (const float4*)(gallery + j * FEAT + kl);
        uint64_t ad0 = 0ull, ad1 = 0ull, ad2 = 0ull, ag = 0ull;
        #pragma unroll 4
        for (int it = 0; it < 8; it++) {
            float4 g = gptr[it * 8];         // stride 32 floats
            int kp = it * 16 + (lane & 7) * 2;   // even pair index
            uint64_t gxy = pack2(g.x, g.y);
            uint64_t gzw = pack2(g.z, g.w);
            ulonglong2 p0 = *(const ulonglong2*)&spp[0][kp];
            ulonglong2 p1 = *(const ulonglong2*)&spp[1][kp];
            ulonglong2 p2 = *(const ulonglong2*)&spp[2][kp];
            fma2(ad0, p0.x, gxy); fma2(ad0, p0.y, gzw);
            fma2(ad1, p1.x, gxy); fma2(ad1, p1.y, gzw);
            fma2(ad2, p2.x, gxy); fma2(ad2, p2.y, gzw);
            fma2(ag,  gxy,  gxy); fma2(ag,  gzw,  gzw);
        }
        float d0, d1, d2, gg, t;
        unpack2(ad0, d0, t); d0 += t;
        unpack2(ad1, d1, t); d1 += t;
        unpack2(ad2, d2, t); d2 += t;
        unpack2(ag,  gg, t); gg += t;
        #pragma unroll
        for (int off = 1; off < 8; off <<= 1) {   // reduce within 8-lane group
            d0 += __shfl_xor_sync(0xffffffffu, d0, off);
            d1 += __shfl_xor_sync(0xffffffffu, d1, off);
            d2 += __shfl_xor_sync(0xffffffffu, d2, off);
            gg += __shfl_xor_sync(0xffffffffu, gg, off);
        }
        if ((lane & 7) == 0) {
            float invg = 1.0f / fmaxf(sqrtf(gg), 1e-12f);
            S[0][j] = d0 * inv3[0] * invg;
            S[1][j] = d1 * inv3[1] * invg;
            S[2][j] = d2 * inv3[2] * invg;
        }
    }
    __syncthreads();

    // ---------------- Phase B: rank sums, 3 rows (verified structure) -------
    int col  = tid % BATCH;
    int half = tid / BATCH;                  // pass 1: row = half; pass 2: row 2

    {   // pass 1: rows 0 (warps 0-11) and 1 (warps 12-23)
        int r  = half;
        int n8 = (base + r) & ~(GROUP - 1);
        float sval = S[r][col];
        float sg[8];
        #pragma unroll
        for (int b = 0; b < 8; b++) sg[b] = sigm(S[r][n8 + b] - sval);
        #pragma unroll
        for (int b = 0; b < 8; b++) {
            #pragma unroll
            for (int off = 16; off > 0; off >>= 1)
                sg[b] += __shfl_down_sync(0xffffffffu, sg[b], off);
        }
        if (lane == 0) {
            #pragma unroll
            for (int b = 0; b < 8; b++) wp[warp][0][b] = sg[b];
        }
    }
    if (half == 0) {                         // pass 2: row 2 (warps 0-11)
        int n8 = (base + 2) & ~(GROUP - 1);
        float sval = S[2][col];
        float sg[8];
        #pragma unroll
        for (int b = 0; b < 8; b++) sg[b] = sigm(S[2][n8 + b] - sval);
        #pragma unroll
        for (int b = 0; b < 8; b++) {
            #pragma unroll
            for (int off = 16; off > 0; off >>= 1)
                sg[b] += __shfl_down_sync(0xffffffffu, sg[b], off);
        }
        if (lane == 0) {
            #pragma unroll
            for (int b = 0; b < 8; b++) wp[warp][1][b] = sg[b];
        }
    }
    __syncthreads();

    float btotal = 0.f;
    if (tid < 32) {                          // threads 0-23: one per (row, b)
        float ratio = 0.f;
        if (tid < 24) {
            int r = tid >> 3, b = tid & 7;
            // row0 -> wp[0..11][0]; row1 -> wp[12..23][0]; row2 -> wp[0..11][1]
            int w0 = (r == 1) ? 12 : 0;
            int s  = (r == 2) ? 1 : 0;
            float allrk = 0.f;
            #pragma unroll
            for (int w = 0; w < 12; w++) allrk += wp[w0 + w][s][b];
            int n8 = (base + r) & ~(GROUP - 1);
            float db = S[r][n8 + b];
            float posrk = 0.f;
            #pragma unroll
            for (int c = 0; c < 8; c++) posrk += sigm(db - S[r][n8 + c]);
            ratio = __fdividef(posrk, allrk);
        }
        #pragma unroll
        for (int off = 16; off > 0; off >>= 1)
            ratio += __shfl_down_sync(0xffffffffu, ratio, off);
        btotal = ratio;
    }
    if (tid == 0) {
        g_partial[blockIdx.x] = btotal;
        __threadfence();
        islast = (atomicAdd(&g_done, 1u) == (unsigned)(NBLK - 1)) ? 1u : 0u;
    }
    __syncthreads();

    // ---------------- Final reduction by the last-done block ----------------
    if (islast) {
        if (tid < NBLK) {
            float v = __ldcg(&g_partial[tid]);
            #pragma unroll
            for (int off = 16; off > 0; off >>= 1)
                v += __shfl_down_sync(0xffffffffu, v, off);
            if (lane == 0) wfin[warp] = v;
        }
        __syncthreads();
        if (tid == 0) {
            float tot = wfin[0] + wfin[1] + wfin[2] + wfin[3];
            out[0] = 1.0f - tot / (float)(GROUP * BATCH);
            g_done = 0;                      // reset for next graph replay
        }
    }
}

extern "C" void kernel_launch(void* const* d_in, const int* in_sizes, int n_in,
                              void* d_out, int out_size) {
    const float* preds   = (const float*)d_in[0];
    const float* gallery = (const float*)d_in[1];
    float* out = (float*)d_out;
    smoothap_kernel<<<NBLK, NT>>>(preds, gallery, out);
}